// round 4
// baseline (speedup 1.0000x reference)
#include <cuda_runtime.h>
#include <cuda_bf16.h>
#include <cstdint>

// Problem constants (from reference)
#define NN    50000      // nodes
#define EE    800000     // edges
#define NODE_D 128
#define EDGE_D 16
#define HID   300

typedef unsigned long long u64;

// ---------------- scratch (device globals; no allocs allowed) ----------------
__device__ float g_inc[NN * EDGE_D + 64];
__device__ float g_agg[(size_t)NN * HID + 64];
__device__ float g_h0[(size_t)NN * HID + 64];
__device__ int   g_cnt[NN];
__device__ int   g_rowptr[NN];
__device__ int   g_cursor[NN];
__device__ int   g_src_sorted[EE];
__device__ float g_w_sorted[EE];

// ---------------- f32x2 helpers ----------------
__device__ __forceinline__ void fma2(u64& c, u64 a, u64 b) {
    asm("fma.rn.f32x2 %0, %1, %2, %0;" : "+l"(c) : "l"(a), "l"(b));
}
__device__ __forceinline__ float2 upk(u64 v) {
    float2 r;
    asm("mov.b64 {%0, %1}, %2;" : "=f"(r.x), "=f"(r.y) : "l"(v));
    return r;
}

// ---------------- kernel 1: zero inc + cnt ----------------
__global__ void zero_kernel(float* __restrict__ inc, int* __restrict__ cnt) {
    int idx = blockIdx.x * blockDim.x + threadIdx.x;
    int stride = gridDim.x * blockDim.x;
    for (int i = idx; i < NN * EDGE_D; i += stride) inc[i] = 0.f;
    for (int i = idx; i < NN; i += stride) cnt[i] = 0;
}

// ---------------- kernel 2: scatter edge features + histogram ----------------
__global__ void edge_scatter_kernel(const float* __restrict__ edge_attr,
                                    const float* __restrict__ edge_weight,
                                    const int* __restrict__ edge_index,
                                    float* __restrict__ inc,
                                    int* __restrict__ cnt) {
    int tid = blockIdx.x * blockDim.x + threadIdx.x;
    if (tid >= EE * EDGE_D) return;
    int e = tid >> 4;
    int d = tid & 15;
    int dst = edge_index[EE + e];
    float w = edge_weight[e];
    atomicAdd(&inc[dst * EDGE_D + d], w * edge_attr[tid]);
    if (d == 0) atomicAdd(&cnt[dst], 1);
}

// ---------------- kernel 3: single-block exclusive scan ----------------
__global__ void scan_kernel(const int* __restrict__ cnt,
                            int* __restrict__ rowptr,
                            int* __restrict__ cursor) {
    __shared__ int part[1024];
    const int n = NN;
    int t = threadIdx.x;
    const int chunk = (n + 1023) / 1024;
    int beg = t * chunk;
    int end = beg + chunk;
    if (beg > n) beg = n;
    if (end > n) end = n;
    int s = 0;
    for (int i = beg; i < end; i++) s += cnt[i];
    part[t] = s;
    __syncthreads();
    for (int off = 1; off < 1024; off <<= 1) {
        int v = (t >= off) ? part[t - off] : 0;
        __syncthreads();
        part[t] += v;
        __syncthreads();
    }
    int run = part[t] - s;
    for (int i = beg; i < end; i++) {
        rowptr[i] = run;
        cursor[i] = run;
        run += cnt[i];
    }
}

// ---------------- kernel 4: bucket edges by dst ----------------
__global__ void fill_kernel(const float* __restrict__ edge_weight,
                            const int* __restrict__ edge_index,
                            int* __restrict__ cursor,
                            int* __restrict__ src_sorted,
                            float* __restrict__ w_sorted) {
    int e = blockIdx.x * blockDim.x + threadIdx.x;
    if (e >= EE) return;
    int src = edge_index[e];
    int dst = edge_index[EE + e];
    int pos = atomicAdd(&cursor[dst], 1);
    src_sorted[pos] = src;
    w_sorted[pos]   = edge_weight[e];
}

// ---------------- GEMM: 128x64 tile, f32x2 inner loop ----------------
// C[M,Nn] = relu( A @ B + bias (+ resid) )
// CONCAT: A col k comes from A (k<K1, ld=K1) else A2 (ld=K-K1). K1,K multiples of 16.
template<bool CONCAT, bool RESID>
__global__ __launch_bounds__(256)
void gemm_f32x2(const float* __restrict__ A, const float* __restrict__ A2, int K1,
                const float* __restrict__ B, const float* __restrict__ bias,
                const float* __restrict__ resid,
                float* __restrict__ C, int M, int Nn, int K) {
    const int BM = 128, BN = 64, BK = 16;
    const int ASTR = BM + 4;                  // 132 floats, rows stay 16B-aligned
    __shared__ __align__(16) float As[BK][ASTR];   // [k][m]
    __shared__ __align__(16) float Bd[BK][2 * BN]; // duplicated pairs (b,b)

    int tid = threadIdx.x;
    int m0 = blockIdx.y * BM;
    int n0 = blockIdx.x * BN;

    // A-tile loader mapping: 2 float4 per thread
    int la_m = tid >> 2;          // 0..63  (+64 for second)
    int la_k = (tid & 3) * 4;     // 0,4,8,12
    // B-tile loader mapping: 1 float4 per thread
    int lb_k = tid >> 4;          // 0..15
    int lb_n = (tid & 15) * 4;    // 0..60

    // compute mapping
    int tx = tid & 15;            // col group: cols n0 + tx*4 .. +3
    int ty = tid >> 4;            // row group: rows m0 + ty*8 .. +7

    u64 acc[4][4];
#pragma unroll
    for (int p = 0; p < 4; p++)
#pragma unroll
        for (int j = 0; j < 4; j++) acc[p][j] = 0ULL;

    float4 ar0, ar1, br;
    const int nt = (K + BK - 1) / BK;

    // ---- prefetch tile 0 into registers ----
    {
        int k0 = 0;
#pragma unroll
        for (int it = 0; it < 2; it++) {
            int gm = m0 + la_m + it * 64;
            int gk = k0 + la_k;
            float4 v = make_float4(0.f, 0.f, 0.f, 0.f);
            if (gm < M) {
                if (CONCAT) {
                    v = (gk < K1) ? *reinterpret_cast<const float4*>(A  + (size_t)gm * K1 + gk)
                                  : *reinterpret_cast<const float4*>(A2 + (size_t)gm * (K - K1) + (gk - K1));
                } else {
                    if (gk + 3 < K) v = *reinterpret_cast<const float4*>(A + (size_t)gm * K + gk);
                }
            }
            if (it == 0) ar0 = v; else ar1 = v;
        }
        int gk = k0 + lb_k, gn = n0 + lb_n;
        float4 v = make_float4(0.f, 0.f, 0.f, 0.f);
        if (gk < K && gn + 3 < Nn) v = *reinterpret_cast<const float4*>(B + (size_t)gk * Nn + gn);
        br = v;
    }

    for (int t = 0; t < nt; t++) {
        // ---- store prefetched tile to smem ----
        As[la_k + 0][la_m]      = ar0.x;
        As[la_k + 1][la_m]      = ar0.y;
        As[la_k + 2][la_m]      = ar0.z;
        As[la_k + 3][la_m]      = ar0.w;
        As[la_k + 0][la_m + 64] = ar1.x;
        As[la_k + 1][la_m + 64] = ar1.y;
        As[la_k + 2][la_m + 64] = ar1.z;
        As[la_k + 3][la_m + 64] = ar1.w;
        *reinterpret_cast<float4*>(&Bd[lb_k][lb_n * 2])     = make_float4(br.x, br.x, br.y, br.y);
        *reinterpret_cast<float4*>(&Bd[lb_k][lb_n * 2 + 4]) = make_float4(br.z, br.z, br.w, br.w);
        __syncthreads();

        // ---- prefetch next tile ----
        if (t + 1 < nt) {
            int k0 = (t + 1) * BK;
#pragma unroll
            for (int it = 0; it < 2; it++) {
                int gm = m0 + la_m + it * 64;
                int gk = k0 + la_k;
                float4 v = make_float4(0.f, 0.f, 0.f, 0.f);
                if (gm < M) {
                    if (CONCAT) {
                        v = (gk < K1) ? *reinterpret_cast<const float4*>(A  + (size_t)gm * K1 + gk)
                                      : *reinterpret_cast<const float4*>(A2 + (size_t)gm * (K - K1) + (gk - K1));
                    } else {
                        if (gk + 3 < K) v = *reinterpret_cast<const float4*>(A + (size_t)gm * K + gk);
                    }
                }
                if (it == 0) ar0 = v; else ar1 = v;
            }
            int gk = k0 + lb_k, gn = n0 + lb_n;
            float4 v = make_float4(0.f, 0.f, 0.f, 0.f);
            if (gk < K && gn + 3 < Nn) v = *reinterpret_cast<const float4*>(B + (size_t)gk * Nn + gn);
            br = v;
        }

        // ---- compute ----
#pragma unroll
        for (int kk = 0; kk < BK; kk++) {
            ulonglong2 aA  = *reinterpret_cast<const ulonglong2*>(&As[kk][ty * 8]);
            ulonglong2 aB  = *reinterpret_cast<const ulonglong2*>(&As[kk][ty * 8 + 4]);
            ulonglong2 b01 = *reinterpret_cast<const ulonglong2*>(&Bd[kk][tx * 8]);
            ulonglong2 b23 = *reinterpret_cast<const ulonglong2*>(&Bd[kk][tx * 8 + 4]);
            fma2(acc[0][0], aA.x, b01.x); fma2(acc[0][1], aA.x, b01.y);
            fma2(acc[0][2], aA.x, b23.x); fma2(acc[0][3], aA.x, b23.y);
            fma2(acc[1][0], aA.y, b01.x); fma2(acc[1][1], aA.y, b01.y);
            fma2(acc[1][2], aA.y, b23.x); fma2(acc[1][3], aA.y, b23.y);
            fma2(acc[2][0], aB.x, b01.x); fma2(acc[2][1], aB.x, b01.y);
            fma2(acc[2][2], aB.x, b23.x); fma2(acc[2][3], aB.x, b23.y);
            fma2(acc[3][0], aB.y, b01.x); fma2(acc[3][1], aB.y, b01.y);
            fma2(acc[3][2], aB.y, b23.x); fma2(acc[3][3], aB.y, b23.y);
        }
        __syncthreads();
    }

    // ---- epilogue ----
    int col0 = n0 + tx * 4;
    float bias4[4];
#pragma unroll
    for (int j = 0; j < 4; j++) bias4[j] = (col0 + j < Nn) ? bias[col0 + j] : 0.f;

#pragma unroll
    for (int p = 0; p < 4; p++) {
        float2 v0 = upk(acc[p][0]);
        float2 v1 = upk(acc[p][1]);
        float2 v2 = upk(acc[p][2]);
        float2 v3 = upk(acc[p][3]);
        float r0[4] = { v0.x, v1.x, v2.x, v3.x };  // row m0+ty*8+2p
        float r1[4] = { v0.y, v1.y, v2.y, v3.y };  // row m0+ty*8+2p+1
#pragma unroll
        for (int e = 0; e < 2; e++) {
            int row = m0 + ty * 8 + 2 * p + e;
            if (row >= M) continue;
            float* rv = e ? r1 : r0;
            if (col0 + 3 < Nn) {
                float4 out;
                float res[4] = {0.f, 0.f, 0.f, 0.f};
                if (RESID) {
                    float4 rr = *reinterpret_cast<const float4*>(resid + (size_t)row * Nn + col0);
                    res[0] = rr.x; res[1] = rr.y; res[2] = rr.z; res[3] = rr.w;
                }
                out.x = fmaxf(rv[0] + bias4[0] + res[0], 0.f);
                out.y = fmaxf(rv[1] + bias4[1] + res[1], 0.f);
                out.z = fmaxf(rv[2] + bias4[2] + res[2], 0.f);
                out.w = fmaxf(rv[3] + bias4[3] + res[3], 0.f);
                *reinterpret_cast<float4*>(C + (size_t)row * Nn + col0) = out;
            } else {
#pragma unroll
                for (int j = 0; j < 4; j++) {
                    int col = col0 + j;
                    if (col >= Nn) continue;
                    float v = rv[j] + bias4[j];
                    if (RESID) v += resid[(size_t)row * Nn + col];
                    C[(size_t)row * Nn + col] = fmaxf(v, 0.f);
                }
            }
        }
    }
}

// ---------------- kernel 6: per-node CSR aggregation (scatter-mean) -----------
__global__ __launch_bounds__(128)
void aggregate_kernel(const float* __restrict__ h0,
                      const int* __restrict__ rowptr,
                      const int* __restrict__ cnt_arr,
                      const int* __restrict__ src_sorted,
                      const float* __restrict__ w_sorted,
                      float* __restrict__ agg) {
    int i = blockIdx.x;
    int t = threadIdx.x;
    int start = rowptr[i];
    int cnt = cnt_arr[i];
    __shared__ int s_src[128];
    __shared__ float s_w[128];
    float acc0 = 0.f, acc1 = 0.f, acc2 = 0.f;
    for (int base = 0; base < cnt; base += 128) {
        int m = cnt - base; if (m > 128) m = 128;
        if (t < m) {
            s_src[t] = src_sorted[start + base + t];
            s_w[t]   = w_sorted[start + base + t];
        }
        __syncthreads();
        for (int j = 0; j < m; j++) {
            const float* row = h0 + (size_t)s_src[j] * HID;
            float w = s_w[j];
            acc0 += w * row[t];
            acc1 += w * row[t + 128];
            if (t + 256 < HID) acc2 += w * row[t + 256];
        }
        __syncthreads();
    }
    float inv = 1.0f / fmaxf((float)cnt, 1.0f);
    float* out = agg + (size_t)i * HID;
    out[t] = acc0 * inv;
    out[t + 128] = acc1 * inv;
    if (t + 256 < HID) out[t + 256] = acc2 * inv;
}

// ---------------- launch ----------------
extern "C" void kernel_launch(void* const* d_in, const int* in_sizes, int n_in,
                              void* d_out, int out_size) {
    const float* x = nullptr;
    const float* edge_attr = nullptr;
    const float* edge_weight = nullptr;
    const float* W0 = nullptr;
    const float* b0 = nullptr;
    const float* W  = nullptr;
    const float* b  = nullptr;
    const int*   edge_index = nullptr;

    for (int i = 0; i < n_in; i++) {
        int s = in_sizes[i];
        switch (s) {
            case NN * NODE_D:      x = (const float*)d_in[i]; break;
            case EE * EDGE_D:      edge_attr = (const float*)d_in[i]; break;
            case EE:               edge_weight = (const float*)d_in[i]; break;
            case (NODE_D + EDGE_D) * HID: W0 = (const float*)d_in[i]; break;
            case HID * HID:        W = (const float*)d_in[i]; break;
            case 2 * EE:           edge_index = (const int*)d_in[i]; break;
            case HID:
                if (!b0) b0 = (const float*)d_in[i];
                else     b  = (const float*)d_in[i];
                break;
            default: break; // node_weight unused
        }
    }
    if (!b) b = b0;

    void *p_inc, *p_agg, *p_h0, *p_cnt, *p_rowptr, *p_cursor, *p_src, *p_w;
    cudaGetSymbolAddress(&p_inc,    g_inc);
    cudaGetSymbolAddress(&p_agg,    g_agg);
    cudaGetSymbolAddress(&p_h0,     g_h0);
    cudaGetSymbolAddress(&p_cnt,    g_cnt);
    cudaGetSymbolAddress(&p_rowptr, g_rowptr);
    cudaGetSymbolAddress(&p_cursor, g_cursor);
    cudaGetSymbolAddress(&p_src,    g_src_sorted);
    cudaGetSymbolAddress(&p_w,      g_w_sorted);

    float* inc        = (float*)p_inc;
    float* agg        = (float*)p_agg;
    int*   cnt        = (int*)p_cnt;
    int*   rowptr     = (int*)p_rowptr;
    int*   cursor     = (int*)p_cursor;
    int*   src_sorted = (int*)p_src;
    float* w_sorted   = (float*)p_w;

    float* h = (float*)d_out;
    float* h0 = (out_size >= 2 * NN * HID) ? (float*)d_out + (size_t)NN * HID
                                           : (float*)p_h0;

    // 1. zero scratch
    zero_kernel<<<2048, 256>>>(inc, cnt);

    // 2. scatter inc + histogram
    edge_scatter_kernel<<<(EE * EDGE_D + 255) / 256, 256>>>(edge_attr, edge_weight,
                                                            edge_index, inc, cnt);

    // 3. scan -> rowptr/cursor
    scan_kernel<<<1, 1024>>>(cnt, rowptr, cursor);

    // 4. bucket edges
    fill_kernel<<<(EE + 255) / 256, 256>>>(edge_weight, edge_index,
                                           cursor, src_sorted, w_sorted);

    // 5. GEMM1: h0 = relu([x | inc] @ W0 + b0)   (K=144, concat)
    {
        dim3 grid((HID + 63) / 64, (NN + 127) / 128);
        gemm_f32x2<true, false><<<grid, 256>>>(x, inc, NODE_D,
                                               W0, b0, nullptr,
                                               h0, NN, HID, NODE_D + EDGE_D);
    }

    // 6. aggregation: agg = scatter_mean(edge_weight * h0[src], dst)
    aggregate_kernel<<<NN, 128>>>(h0, rowptr, cnt, src_sorted, w_sorted, agg);

    // 7. GEMM2: h = relu(h0 + agg @ W + b)   (K=300)
    {
        dim3 grid((HID + 63) / 64, (NN + 127) / 128);
        gemm_f32x2<false, true><<<grid, 256>>>(agg, nullptr, 0,
                                               W, b, h0,
                                               h, NN, HID, HID);
    }
}

// round 6
// speedup vs baseline: 1.6459x; 1.6459x over previous
#include <cuda_runtime.h>
#include <cuda_bf16.h>
#include <cstdint>

#define NN    50000
#define EE    800000
#define NODE_D 128
#define EDGE_D 16
#define HID   300

#define NPAD  384
#define K1PAD 192           // GEMM1 K=144 -> 3 chunks of 64
#define K2PAD 320           // GEMM2 K=300 -> 5 chunks of 64

typedef unsigned long long u64;

// ---------------- scratch (device globals; no allocs allowed) ----------------
__device__ float g_inc[NN * EDGE_D + 64];
__device__ float g_agg[(size_t)NN * HID + 64];
__device__ float g_h0[(size_t)NN * HID + 64];
__device__ int   g_cnt[NN];
__device__ int   g_rowptr[NN];
__device__ int   g_cursor[NN];
__device__ int   g_src_sorted[EE];
__device__ float g_w_sorted[EE];
__device__ __nv_bfloat16 g_w0t_hi[NPAD * K1PAD];
__device__ __nv_bfloat16 g_w0t_lo[NPAD * K1PAD];
__device__ __nv_bfloat16 g_wt_hi[NPAD * K2PAD];
__device__ __nv_bfloat16 g_wt_lo[NPAD * K2PAD];

// ---------------- warp MMA helpers ----------------
__device__ __forceinline__ uint32_t smem_u32(const void* p) {
    return (uint32_t)__cvta_generic_to_shared(p);
}
__device__ __forceinline__ void ldsm_x4(uint32_t* r, uint32_t addr) {
    asm volatile("ldmatrix.sync.aligned.m8n8.x4.shared.b16 {%0,%1,%2,%3}, [%4];"
                 : "=r"(r[0]), "=r"(r[1]), "=r"(r[2]), "=r"(r[3]) : "r"(addr));
}
__device__ __forceinline__ void mma_bf16(float* d, const uint32_t* a, const uint32_t* b) {
    asm volatile(
        "mma.sync.aligned.m16n8k16.row.col.f32.bf16.bf16.f32 "
        "{%0,%1,%2,%3}, {%4,%5,%6,%7}, {%8,%9}, {%0,%1,%2,%3};"
        : "+f"(d[0]), "+f"(d[1]), "+f"(d[2]), "+f"(d[3])
        : "r"(a[0]), "r"(a[1]), "r"(a[2]), "r"(a[3]), "r"(b[0]), "r"(b[1]));
}

// ---------------- kernel 1: zero inc + cnt ----------------
__global__ void zero_kernel(float* __restrict__ inc, int* __restrict__ cnt) {
    int idx = blockIdx.x * blockDim.x + threadIdx.x;
    int stride = gridDim.x * blockDim.x;
    for (int i = idx; i < NN * EDGE_D; i += stride) inc[i] = 0.f;
    for (int i = idx; i < NN; i += stride) cnt[i] = 0;
}

// ---------------- kernel 2: scatter edge features + histogram ----------------
__global__ void edge_scatter_kernel(const float* __restrict__ edge_attr,
                                    const float* __restrict__ edge_weight,
                                    const int* __restrict__ edge_index,
                                    float* __restrict__ inc,
                                    int* __restrict__ cnt) {
    int tid = blockIdx.x * blockDim.x + threadIdx.x;
    if (tid >= EE * EDGE_D) return;
    int e = tid >> 4;
    int d = tid & 15;
    int dst = edge_index[EE + e];
    float w = edge_weight[e];
    atomicAdd(&inc[dst * EDGE_D + d], w * edge_attr[tid]);
    if (d == 0) atomicAdd(&cnt[dst], 1);
}

// ---------------- kernel 3: single-block exclusive scan ----------------
__global__ void scan_kernel(const int* __restrict__ cnt,
                            int* __restrict__ rowptr,
                            int* __restrict__ cursor) {
    __shared__ int part[1024];
    const int n = NN;
    int t = threadIdx.x;
    const int chunk = (n + 1023) / 1024;
    int beg = t * chunk;
    int end = beg + chunk;
    if (beg > n) beg = n;
    if (end > n) end = n;
    int s = 0;
    for (int i = beg; i < end; i++) s += cnt[i];
    part[t] = s;
    __syncthreads();
    for (int off = 1; off < 1024; off <<= 1) {
        int v = (t >= off) ? part[t - off] : 0;
        __syncthreads();
        part[t] += v;
        __syncthreads();
    }
    int run = part[t] - s;
    for (int i = beg; i < end; i++) {
        rowptr[i] = run;
        cursor[i] = run;
        run += cnt[i];
    }
}

// ---------------- kernel 4: bucket edges by dst ----------------
__global__ void fill_kernel(const float* __restrict__ edge_weight,
                            const int* __restrict__ edge_index,
                            int* __restrict__ cursor,
                            int* __restrict__ src_sorted,
                            float* __restrict__ w_sorted) {
    int e = blockIdx.x * blockDim.x + threadIdx.x;
    if (e >= EE) return;
    int src = edge_index[e];
    int dst = edge_index[EE + e];
    int pos = atomicAdd(&cursor[dst], 1);
    src_sorted[pos] = src;
    w_sorted[pos]   = edge_weight[e];
}

// ------------- weight prep: transpose + bf16 split + zero-pad ---------------
// src: [K, Nn] fp32. dst[n*KPAD+k] = src[k*Nn+n] split into hi/lo bf16.
__global__ void prep_weight(const float* __restrict__ src,
                            __nv_bfloat16* __restrict__ hi,
                            __nv_bfloat16* __restrict__ lo,
                            int K, int Nn, int KPAD) {
    int idx = blockIdx.x * blockDim.x + threadIdx.x;
    if (idx >= NPAD * KPAD) return;
    int n = idx / KPAD;
    int k = idx - n * KPAD;
    float v = (k < K && n < Nn) ? src[(size_t)k * Nn + n] : 0.f;
    __nv_bfloat16 h = __float2bfloat16(v);
    float r = v - __bfloat162float(h);
    hi[idx] = h;
    lo[idx] = __float2bfloat16(r);
}

// ---------------- split-bf16 HMMA GEMM ---------------------------------------
// C[M,Nn] = relu( A @ W + bias (+resid) ); W pre-transposed/split: Bt[n][k].
// CTA: 128x128 tile, K-chunks of 64. 8 warps as 4(m) x 2(n), warp tile 32x64.
#define ASTR 72                         // smem k-stride (bf16), conflict-free
#define GEMM_SMEM (4 * 128 * ASTR * 2)  // 73728 B
template<bool CONCAT, bool RESID>
__global__ __launch_bounds__(256)
void gemm_hmma(const float* __restrict__ A, const float* __restrict__ A2,
               const __nv_bfloat16* __restrict__ Bhi, const __nv_bfloat16* __restrict__ Blo,
               const float* __restrict__ bias, const float* __restrict__ resid,
               float* __restrict__ C, int M, int Nn, int K, int K1, int KPAD) {
    extern __shared__ __nv_bfloat16 sm[];
    __nv_bfloat16* Ah = sm;
    __nv_bfloat16* Al = sm + 128 * ASTR;
    __nv_bfloat16* Bh = sm + 2 * 128 * ASTR;
    __nv_bfloat16* Bl = sm + 3 * 128 * ASTR;

    int tid = threadIdx.x;
    int wid = tid >> 5, lid = tid & 31;
    int warp_m = wid >> 1;          // 0..3
    int warp_n = wid & 1;           // 0..1
    int m0 = blockIdx.y * 128;
    int n0 = blockIdx.x * 128;

    float acc[2][8][4];
#pragma unroll
    for (int i = 0; i < 2; i++)
#pragma unroll
        for (int j = 0; j < 8; j++)
#pragma unroll
            for (int q = 0; q < 4; q++) acc[i][j][q] = 0.f;

    // ldmatrix lane addressing pieces
    int a_row_l = lid & 15;          // row within m16
    int a_kh    = (lid >> 4) * 8;    // k half
    int b_mat   = lid >> 3;          // 0..3
    int b_rr    = lid & 7;

    const int nchunk = KPAD >> 6;
    for (int c = 0; c < nchunk; c++) {
        int kbase = c << 6;
        // ---- fill A_hi/A_lo: 128 rows x 64 k (fp32 -> split bf16) ----
        for (int it = tid; it < 1024; it += 256) {
            int row = it >> 3, grp = it & 7;
            int gm = m0 + row;
            int gk = kbase + grp * 8;
            float v[8];
            bool fast = false;
            if (gm < M && gk + 8 <= K) {
                const float* p;
                if (CONCAT) p = (gk < K1) ? (A + (size_t)gm * K1 + gk)
                                          : (A2 + (size_t)gm * (K - K1) + (gk - K1));
                else        p = A + (size_t)gm * K + gk;
                float4 u0 = *reinterpret_cast<const float4*>(p);
                float4 u1 = *reinterpret_cast<const float4*>(p + 4);
                v[0]=u0.x; v[1]=u0.y; v[2]=u0.z; v[3]=u0.w;
                v[4]=u1.x; v[5]=u1.y; v[6]=u1.z; v[7]=u1.w;
                fast = true;
            }
            if (!fast) {
#pragma unroll
                for (int i = 0; i < 8; i++) {
                    int kk = gk + i;
                    float val = 0.f;
                    if (gm < M && kk < K) {
                        if (CONCAT) val = (kk < K1) ? A[(size_t)gm * K1 + kk]
                                                    : A2[(size_t)gm * (K - K1) + (kk - K1)];
                        else        val = A[(size_t)gm * K + kk];
                    }
                    v[i] = val;
                }
            }
            uint32_t hw[4], lw[4];
#pragma unroll
            for (int i = 0; i < 4; i++) {
                __nv_bfloat16 h0b = __float2bfloat16(v[2*i]);
                __nv_bfloat16 h1b = __float2bfloat16(v[2*i+1]);
                float r0 = v[2*i]   - __bfloat162float(h0b);
                float r1 = v[2*i+1] - __bfloat162float(h1b);
                __nv_bfloat16 l0b = __float2bfloat16(r0);
                __nv_bfloat16 l1b = __float2bfloat16(r1);
                hw[i] = (uint32_t)__bfloat16_as_ushort(h0b) | ((uint32_t)__bfloat16_as_ushort(h1b) << 16);
                lw[i] = (uint32_t)__bfloat16_as_ushort(l0b) | ((uint32_t)__bfloat16_as_ushort(l1b) << 16);
            }
            int off = row * ASTR + grp * 8;
            *reinterpret_cast<uint4*>(Ah + off) = make_uint4(hw[0], hw[1], hw[2], hw[3]);
            *reinterpret_cast<uint4*>(Al + off) = make_uint4(lw[0], lw[1], lw[2], lw[3]);
        }
        // ---- fill B_hi/B_lo: 128 n-rows x 64 k (bf16 copy) ----
        for (int it = tid; it < 1024; it += 256) {
            int row = it >> 3, grp = it & 7;
            size_t gidx = (size_t)(n0 + row) * KPAD + kbase + grp * 8;
            int off = row * ASTR + grp * 8;
            *reinterpret_cast<uint4*>(Bh + off) = *reinterpret_cast<const uint4*>(Bhi + gidx);
            *reinterpret_cast<uint4*>(Bl + off) = *reinterpret_cast<const uint4*>(Blo + gidx);
        }
        __syncthreads();

        // ---- MMA phase ----
        int rem = K - kbase;
        int ksteps = (rem + 15) >> 4;
        if (ksteps > 4) ksteps = 4;
        for (int ks = 0; ks < ksteps; ks++) {
            int k0 = ks * 16;
            uint32_t ah[2][4], al[2][4];
#pragma unroll
            for (int i = 0; i < 2; i++) {
                int arow = warp_m * 32 + i * 16 + a_row_l;
                uint32_t addr_h = smem_u32(Ah + arow * ASTR + k0 + a_kh);
                uint32_t addr_l = smem_u32(Al + arow * ASTR + k0 + a_kh);
                ldsm_x4(ah[i], addr_h);
                ldsm_x4(al[i], addr_l);
            }
#pragma unroll
            for (int jp = 0; jp < 4; jp++) {
                int brow = warp_n * 64 + (jp * 2 + (b_mat >> 1)) * 8 + b_rr;
                int bk   = k0 + (b_mat & 1) * 8;
                uint32_t bh[4], bl[4];
                ldsm_x4(bh, smem_u32(Bh + brow * ASTR + bk));
                ldsm_x4(bl, smem_u32(Bl + brow * ASTR + bk));
#pragma unroll
                for (int i = 0; i < 2; i++) {
                    mma_bf16(acc[i][2*jp],   ah[i], &bh[0]);
                    mma_bf16(acc[i][2*jp],   al[i], &bh[0]);
                    mma_bf16(acc[i][2*jp],   ah[i], &bl[0]);
                    mma_bf16(acc[i][2*jp+1], ah[i], &bh[2]);
                    mma_bf16(acc[i][2*jp+1], al[i], &bh[2]);
                    mma_bf16(acc[i][2*jp+1], ah[i], &bl[2]);
                }
            }
        }
        __syncthreads();
    }

    // ---- epilogue: bias (+resid) + relu ----
    int tq = lid >> 2;          // 0..7
    int tr = lid & 3;           // 0..3
    int row_base = m0 + warp_m * 32 + tq;
    int col_base = n0 + warp_n * 64 + tr * 2;
#pragma unroll
    for (int i = 0; i < 2; i++) {
#pragma unroll
        for (int j = 0; j < 8; j++) {
            int col = col_base + j * 8;
            if (col >= Nn) continue;
            float2 bs = *reinterpret_cast<const float2*>(bias + col);
#pragma unroll
            for (int half = 0; half < 2; half++) {
                int row = row_base + i * 16 + half * 8;
                if (row >= M) continue;
                float v0 = acc[i][j][2*half + 0] + bs.x;
                float v1 = acc[i][j][2*half + 1] + bs.y;
                if (RESID) {
                    float2 rr = *reinterpret_cast<const float2*>(resid + (size_t)row * Nn + col);
                    v0 += rr.x; v1 += rr.y;
                }
                float2 o;
                o.x = fmaxf(v0, 0.f);
                o.y = fmaxf(v1, 0.f);
                *reinterpret_cast<float2*>(C + (size_t)row * Nn + col) = o;
            }
        }
    }
}

// ---------------- per-node CSR aggregation (scatter-mean) --------------------
__global__ __launch_bounds__(128)
void aggregate_kernel(const float* __restrict__ h0,
                      const int* __restrict__ rowptr,
                      const int* __restrict__ cnt_arr,
                      const int* __restrict__ src_sorted,
                      const float* __restrict__ w_sorted,
                      float* __restrict__ agg) {
    int i = blockIdx.x;
    int t = threadIdx.x;
    int start = rowptr[i];
    int cnt = cnt_arr[i];
    __shared__ int s_src[128];
    __shared__ float s_w[128];
    float acc0 = 0.f, acc1 = 0.f, acc2 = 0.f;
    for (int base = 0; base < cnt; base += 128) {
        int m = cnt - base; if (m > 128) m = 128;
        if (t < m) {
            s_src[t] = src_sorted[start + base + t];
            s_w[t]   = w_sorted[start + base + t];
        }
        __syncthreads();
        for (int j = 0; j < m; j++) {
            const float* row = h0 + (size_t)s_src[j] * HID;
            float w = s_w[j];
            acc0 += w * row[t];
            acc1 += w * row[t + 128];
            if (t + 256 < HID) acc2 += w * row[t + 256];
        }
        __syncthreads();
    }
    float inv = 1.0f / fmaxf((float)cnt, 1.0f);
    float* out = agg + (size_t)i * HID;
    out[t] = acc0 * inv;
    out[t + 128] = acc1 * inv;
    if (t + 256 < HID) out[t + 256] = acc2 * inv;
}

// ---------------- launch ----------------
extern "C" void kernel_launch(void* const* d_in, const int* in_sizes, int n_in,
                              void* d_out, int out_size) {
    const float* x = nullptr;
    const float* edge_attr = nullptr;
    const float* edge_weight = nullptr;
    const float* W0 = nullptr;
    const float* b0 = nullptr;
    const float* W  = nullptr;
    const float* b  = nullptr;
    const int*   edge_index = nullptr;

    for (int i = 0; i < n_in; i++) {
        int s = in_sizes[i];
        switch (s) {
            case NN * NODE_D:      x = (const float*)d_in[i]; break;
            case EE * EDGE_D:      edge_attr = (const float*)d_in[i]; break;
            case EE:               edge_weight = (const float*)d_in[i]; break;
            case (NODE_D + EDGE_D) * HID: W0 = (const float*)d_in[i]; break;
            case HID * HID:        W = (const float*)d_in[i]; break;
            case 2 * EE:           edge_index = (const int*)d_in[i]; break;
            case HID:
                if (!b0) b0 = (const float*)d_in[i];
                else     b  = (const float*)d_in[i];
                break;
            default: break; // node_weight unused
        }
    }
    if (!b) b = b0;

    void *p_inc, *p_agg, *p_h0, *p_cnt, *p_rowptr, *p_cursor, *p_src, *p_w;
    void *p_w0h, *p_w0l, *p_wh, *p_wl;
    cudaGetSymbolAddress(&p_inc,    g_inc);
    cudaGetSymbolAddress(&p_agg,    g_agg);
    cudaGetSymbolAddress(&p_h0,     g_h0);
    cudaGetSymbolAddress(&p_cnt,    g_cnt);
    cudaGetSymbolAddress(&p_rowptr, g_rowptr);
    cudaGetSymbolAddress(&p_cursor, g_cursor);
    cudaGetSymbolAddress(&p_src,    g_src_sorted);
    cudaGetSymbolAddress(&p_w,      g_w_sorted);
    cudaGetSymbolAddress(&p_w0h,    g_w0t_hi);
    cudaGetSymbolAddress(&p_w0l,    g_w0t_lo);
    cudaGetSymbolAddress(&p_wh,     g_wt_hi);
    cudaGetSymbolAddress(&p_wl,     g_wt_lo);

    float* inc        = (float*)p_inc;
    float* agg        = (float*)p_agg;
    int*   cnt        = (int*)p_cnt;
    int*   rowptr     = (int*)p_rowptr;
    int*   cursor     = (int*)p_cursor;
    int*   src_sorted = (int*)p_src;
    float* w_sorted   = (float*)p_w;

    float* h = (float*)d_out;
    float* h0 = (out_size >= 2 * NN * HID) ? (float*)d_out + (size_t)NN * HID
                                           : (float*)p_h0;

    cudaFuncSetAttribute(gemm_hmma<true,  false>,
                         cudaFuncAttributeMaxDynamicSharedMemorySize, GEMM_SMEM);
    cudaFuncSetAttribute(gemm_hmma<false, true>,
                         cudaFuncAttributeMaxDynamicSharedMemorySize, GEMM_SMEM);

    // 1. zero scratch
    zero_kernel<<<2048, 256>>>(inc, cnt);

    // 1b. weight prep (transpose + split + pad)
    prep_weight<<<(NPAD * K1PAD + 255) / 256, 256>>>(W0, (__nv_bfloat16*)p_w0h,
                                                     (__nv_bfloat16*)p_w0l,
                                                     NODE_D + EDGE_D, HID, K1PAD);
    prep_weight<<<(NPAD * K2PAD + 255) / 256, 256>>>(W, (__nv_bfloat16*)p_wh,
                                                     (__nv_bfloat16*)p_wl,
                                                     HID, HID, K2PAD);

    // 2. scatter inc + histogram
    edge_scatter_kernel<<<(EE * EDGE_D + 255) / 256, 256>>>(edge_attr, edge_weight,
                                                            edge_index, inc, cnt);

    // 3. scan -> rowptr/cursor
    scan_kernel<<<1, 1024>>>(cnt, rowptr, cursor);

    // 4. bucket edges
    fill_kernel<<<(EE + 255) / 256, 256>>>(edge_weight, edge_index,
                                           cursor, src_sorted, w_sorted);

    // 5. GEMM1: h0 = relu([x | inc] @ W0 + b0)   (K=144)
    {
        dim3 grid(NPAD / 128, (NN + 127) / 128);
        gemm_hmma<true, false><<<grid, 256, GEMM_SMEM>>>(
            x, inc, (__nv_bfloat16*)p_w0h, (__nv_bfloat16*)p_w0l,
            b0, nullptr, h0, NN, HID, NODE_D + EDGE_D, NODE_D, K1PAD);
    }

    // 6. aggregation: agg = scatter_mean(edge_weight * h0[src], dst)
    aggregate_kernel<<<NN, 128>>>(h0, rowptr, cnt, src_sorted, w_sorted, agg);

    // 7. GEMM2: h = relu(h0 + agg @ W + b)   (K=300)
    {
        dim3 grid(NPAD / 128, (NN + 127) / 128);
        gemm_hmma<false, true><<<grid, 256, GEMM_SMEM>>>(
            agg, nullptr, (__nv_bfloat16*)p_wh, (__nv_bfloat16*)p_wl,
            b, h0, h, NN, HID, HID, 0, K2PAD);
    }
}